// round 10
// baseline (speedup 1.0000x reference)
#include <cuda_runtime.h>

#define AR_P 64
#define AR_T 65536
#define HLEN 65536
#define NB   64          // persistent grid for kAB
#define NT   256

__device__ __align__(16) float g_hpad[AR_P + HLEN];  // h with 64 leading zeros
__device__ __align__(16) float g_means[AR_T];        // bias * cumsum(h)
__device__ float g_part[NB];                         // per-segment sums
__device__ unsigned g_bar_count = 0;                 // returns to 0 every barrier
__device__ unsigned g_bar_gen   = 0;                 // monotonic, replay-safe

// ---------------------------------------------------------------------------
// Grid-wide barrier (canonical gen-counter pattern; all NB CTAs co-resident).
// ---------------------------------------------------------------------------
__device__ __forceinline__ void grid_bar() {
    __syncthreads();
    if (threadIdx.x == 0) {
        __threadfence();
        const unsigned g = *((volatile unsigned*)&g_bar_gen);
        if (atomicAdd(&g_bar_count, 1u) == NB - 1u) {
            atomicExch(&g_bar_count, 0u);
            __threadfence();
            atomicAdd(&g_bar_gen, 1u);
        } else {
            while (*((volatile unsigned*)&g_bar_gen) == g) { }
        }
        __threadfence();
    }
    __syncthreads();
}

// ---------------------------------------------------------------------------
// Conflict-free 64-tap convolution for 4 consecutive outputs.
// out[r] = sum_{i=0}^{63} src[base0 + r - i] * phi[i], r = 0..3.
// src 16B-aligned (shared OR global), base0 multiple of 4.
// ---------------------------------------------------------------------------
__device__ __forceinline__ void conv4_f4(const float* __restrict__ src, int base0,
                                         const float* __restrict__ phi,
                                         float& a0, float& a1, float& a2, float& a3) {
    const float4 va = *reinterpret_cast<const float4*>(&src[base0]);
    const float4 vb = *reinterpret_cast<const float4*>(&src[base0 - 4]);
    float v0 = vb.x, v1 = vb.y, v2 = vb.z, v3 = vb.w;
    float v4 = va.x, v5 = va.y, v6 = va.z, v7 = va.w;
    a0 = 0.f; a1 = 0.f; a2 = 0.f; a3 = 0.f;
    #pragma unroll
    for (int i4 = 0; i4 < 16; i4++) {
        if (i4 > 0) {
            v4 = v0; v5 = v1; v6 = v2; v7 = v3;
            const float4 nv = *reinterpret_cast<const float4*>(&src[base0 - 4 - 4 * i4]);
            v0 = nv.x; v1 = nv.y; v2 = nv.z; v3 = nv.w;
        }
        const float4 p = *reinterpret_cast<const float4*>(&phi[4 * i4]);
        a0 += v4 * p.x; a1 += v5 * p.x; a2 += v6 * p.x; a3 += v7 * p.x;
        a0 += v3 * p.y; a1 += v4 * p.y; a2 += v5 * p.y; a3 += v6 * p.y;
        a0 += v2 * p.z; a1 += v3 * p.z; a2 += v4 * p.z; a3 += v5 * p.z;
        a0 += v1 * p.w; a1 += v2 * p.w; a2 += v3 * p.w; a3 += v4 * p.w;
    }
}

// 4-way-split 64-tap dot: returns sum_j A[abase + j] * B[btop - j]
__device__ __forceinline__ float dot64_4acc_fwd_rev(const float* __restrict__ A, int abase,
                                                    const float* __restrict__ B, int btop) {
    float s0 = 0.f, s1 = 0.f, s2 = 0.f, s3 = 0.f;
    #pragma unroll
    for (int j = 0; j < AR_P; j += 4) {
        s0 += A[abase + j + 0] * B[btop - j - 0];
        s1 += A[abase + j + 1] * B[btop - j - 1];
        s2 += A[abase + j + 2] * B[btop - j - 2];
        s3 += A[abase + j + 3] * B[btop - j - 3];
    }
    return (s0 + s1) + (s2 + s3);
}

// ---------------------------------------------------------------------------
// kAB: persistent 64-block kernel.
//   phase A (block 0): h[0..2048) in smem, publish to global.
//   phase B (all):     doubling levels 2048 -> 65536 in global (L2-hot).
//   phase C (all):     segmented prefix sum -> g_means = bias * cumsum(h).
// ---------------------------------------------------------------------------
__global__ __launch_bounds__(NT) void kAB(const float* __restrict__ params,
                                          const float* __restrict__ bias) {
    __shared__ __align__(16) float Pp[2 * AR_P];      // params + 64 zeros
    __shared__ __align__(16) float hs[AR_P + 2048];   // block-0 staging
    __shared__ __align__(16) float phi[AR_P];
    __shared__ __align__(16) float tailh[AR_P];
    __shared__ float wsum[NT / 32];
    __shared__ float pscan[NB];

    const int tid = threadIdx.x;
    const int lane = tid & 31;
    const int wid = tid >> 5;
    const int blk = blockIdx.x;

    if (tid < 2 * AR_P) Pp[tid] = (tid < AR_P) ? params[tid] : 0.0f;
    __syncthreads();

    // ================= phase A : block 0 only =================
    if (blk == 0) {
        if (tid < AR_P) hs[tid] = 0.0f;      // left zero pad h_{-64..-1}
        if (tid == 0) hs[AR_P] = 1.0f;       // h_0 = 1
        __syncthreads();

        // levels n = 1..32 : scalar, warp 0 only
        if (tid < 32) {
            for (int n = 1; n < AR_P; n <<= 1) {
                #pragma unroll 2
                for (int i = lane; i < AR_P; i += 32)
                    phi[i] = dot64_4acc_fwd_rev(Pp, i, hs, AR_P + n - 1);
                __syncwarp();
                if (lane < n)
                    hs[AR_P + n + lane] = dot64_4acc_fwd_rev(phi, 0, hs, AR_P + lane);
                __syncwarp();
            }
            // levels n = 64, 128 : float4 path, still warp 0
            for (int n = AR_P; n < 256; n <<= 1) {
                #pragma unroll 2
                for (int i = lane; i < AR_P; i += 32)
                    phi[i] = dot64_4acc_fwd_rev(Pp, i, hs, AR_P + n - 1);
                __syncwarp();
                const int nt4 = n >> 2;
                for (int t = lane; t < nt4; t += 32) {
                    float a0, a1, a2, a3;
                    conv4_f4(hs, AR_P + 4 * t, phi, a0, a1, a2, a3);
                    *reinterpret_cast<float4*>(&hs[AR_P + n + 4 * t]) =
                        make_float4(a0, a1, a2, a3);
                }
                __syncwarp();
            }
        }
        __syncthreads();

        // levels n = 256, 512, 1024 : full block, smem
        for (int n = 256; n < 2048; n <<= 1) {
            if (tid < AR_P)
                phi[tid] = dot64_4acc_fwd_rev(Pp, tid, hs, AR_P + n - 1);
            __syncthreads();
            const int nt4 = n >> 2;
            if (tid < nt4) {
                float a0, a1, a2, a3;
                conv4_f4(hs, AR_P + 4 * tid, phi, a0, a1, a2, a3);
                *reinterpret_cast<float4*>(&hs[AR_P + n + 4 * tid]) =
                    make_float4(a0, a1, a2, a3);
            }
            __syncthreads();
        }

        // publish pad + h[0..2048)
        const float4* s4 = reinterpret_cast<const float4*>(hs);
        float4* d4 = reinterpret_cast<float4*>(g_hpad);
        for (int q = tid; q < (AR_P + 2048) / 4; q += NT) d4[q] = s4[q];
    }
    grid_bar();   // h[0..2048) visible chip-wide

    // ================= phase B : distributed doubling =================
    #pragma unroll
    for (int N = 2048; N < HLEN; N <<= 1) {
        if (tid < AR_P / 4)
            reinterpret_cast<float4*>(tailh)[tid] =
                reinterpret_cast<const float4*>(&g_hpad[N])[tid];   // h[N-64..N)
        __syncthreads();
        if (tid < AR_P)
            phi[tid] = dot64_4acc_fwd_rev(Pp, tid, tailh, AR_P - 1);
        __syncthreads();
        const int slots = N >> 2;                     // float4 outputs this level
        for (int s = blk * NT + tid; s < slots; s += NB * NT) {
            const int b0 = 4 * s;
            float a0, a1, a2, a3;
            conv4_f4(&g_hpad[AR_P], b0, phi, a0, a1, a2, a3);
            *reinterpret_cast<float4*>(&g_hpad[AR_P + N + b0]) =
                make_float4(a0, a1, a2, a3);
        }
        grid_bar();
    }

    // ================= phase C : prefix sum -> means =================
    const float bv = bias[0];
    const int seg = blk * (HLEN / NB);                // 1024 elems per block
    const float4 x = *reinterpret_cast<const float4*>(&g_hpad[AR_P + seg + tid * 4]);
    const float tsum = (x.x + x.y) + (x.z + x.w);

    // block reduction of segment sum
    float r = tsum;
    #pragma unroll
    for (int o = 16; o > 0; o >>= 1) r += __shfl_down_sync(0xffffffffu, r, o);
    if (lane == 0) wsum[wid] = r;
    __syncthreads();
    if (tid == 0) {
        float t = 0.f;
        #pragma unroll
        for (int w = 0; w < NT / 32; w++) t += wsum[w];
        g_part[blk] = t;
    }
    grid_bar();

    // scan the 64 segment partials (warp 0, 2 halves)
    if (tid < 32) {
        float a = g_part[tid];
        float b = g_part[tid + 32];
        #pragma unroll
        for (int o = 1; o < 32; o <<= 1) {
            const float t = __shfl_up_sync(0xffffffffu, a, o);
            if (lane >= o) a += t;
        }
        const float tot = __shfl_sync(0xffffffffu, a, 31);
        #pragma unroll
        for (int o = 1; o < 32; o <<= 1) {
            const float t = __shfl_up_sync(0xffffffffu, b, o);
            if (lane >= o) b += t;
        }
        pscan[tid] = a;
        pscan[tid + 32] = b + tot;
    }

    // block scan of per-thread sums
    float inc = tsum;
    #pragma unroll
    for (int o = 1; o < 32; o <<= 1) {
        const float t = __shfl_up_sync(0xffffffffu, inc, o);
        if (lane >= o) inc += t;
    }
    if (lane == 31) wsum[wid] = inc;
    __syncthreads();
    float wbase = 0.f;
    #pragma unroll
    for (int w = 0; w < NT / 32; w++) wbase += (w < wid) ? wsum[w] : 0.f;

    const float segbase = (blk > 0) ? pscan[blk - 1] : 0.0f;
    float run = segbase + wbase + (inc - tsum);
    float4 mo;
    run += x.x; mo.x = bv * run;
    run += x.y; mo.y = bv * run;
    run += x.z; mo.z = bv * run;
    run += x.w; mo.w = bv * run;
    *reinterpret_cast<float4*>(&g_means[seg + tid * 4]) = mo;
}

// ---------------------------------------------------------------------------
// k3: out[b,t] = means[t] + 0.3*noise[b,t]  (float4 streaming)
// ---------------------------------------------------------------------------
__global__ __launch_bounds__(256) void k3_out(const float4* __restrict__ noise,
                                              float4* __restrict__ out) {
    const int idx = blockIdx.x * 256 + threadIdx.x;
    const int t4 = idx & (AR_T / 4 - 1);
    const float4 nz = __ldcs(&noise[idx]);                           // stream
    const float4 mn = reinterpret_cast<const float4*>(g_means)[t4];  // L2-resident
    float4 r;
    r.x = fmaf(0.3f, nz.x, mn.x);
    r.y = fmaf(0.3f, nz.y, mn.y);
    r.z = fmaf(0.3f, nz.z, mn.z);
    r.w = fmaf(0.3f, nz.w, mn.w);
    __stcs(&out[idx], r);                                            // evict-first
}

extern "C" void kernel_launch(void* const* d_in, const int* in_sizes, int n_in,
                              void* d_out, int out_size) {
    // identify inputs by element count (params=64, bias=1, noise=256*65536)
    const float* params = nullptr;
    const float* bias   = nullptr;
    const float* noise  = nullptr;
    for (int i = 0; i < n_in; i++) {
        if (in_sizes[i] == AR_P)      params = (const float*)d_in[i];
        else if (in_sizes[i] == 1)    bias   = (const float*)d_in[i];
        else                          noise  = (const float*)d_in[i];
    }

    kAB<<<NB, NT>>>(params, bias);

    const int total4 = out_size / 4;          // 4,194,304 float4s
    k3_out<<<total4 / 256, 256>>>((const float4*)noise, (float4*)d_out);
}